// round 14
// baseline (speedup 1.0000x reference)
#include <cuda_runtime.h>
#include <cuda_fp16.h>
#include <math.h>
#include <stdint.h>

// ---------------------------------------------------------------- constants
#define B_  32
#define S_  2048
#define H_  1024
#define M_  (S_ * B_)          // 65536 flattened key rows (m = s*B + b)
#define SC_ 32                 // context split-K chunks
#define SCHUNK_ (S_ / SC_)     // 64

#define NSTAGE_ 16             // K chunks of 64 elements
#define STAGEB_ 32768          // bytes/stage: A 16K (2 subs) + B 16K (2 subs)
#define QSOFF_  (2 * STAGEB_)  // 65536
#define SMEMTOT_ (QSOFF_ + 16384)   // 81920 (qw slice 128n x 32b floats)
#define NPLANES_ 16            // 8 n-blocks x 2 warp-cols

// ---------------------------------------------------------------- scratch
__device__ __half g_keyh[(size_t)M_ * H_];     // fp16(key), 128 MB
__device__ __half g_UaT[H_ * H_];              // fp16(Ua^T) (rows n, cols k)
__device__ float g_qwT[H_ * B_];               // qw transposed [n][b]
__device__ float g_part[(size_t)NPLANES_ * M_];// [m][plane] score partials
__device__ float g_ctxp[SC_ * B_ * H_];
__device__ float g_wfallback[B_ * S_];

// ---------------------------------------------------------------- asm helpers
__device__ __forceinline__ uint32_t smem_u32(const void* p) {
    uint32_t a;
    asm("{ .reg .u64 t; cvta.to.shared.u64 t, %1; cvt.u32.u64 %0, t; }"
        : "=r"(a) : "l"(p));
    return a;
}

#define CP16(dst, src) \
    asm volatile("cp.async.cg.shared.global [%0], [%1], 16;" \
                 :: "r"(dst), "l"(src) : "memory")
#define CP_COMMIT()  asm volatile("cp.async.commit_group;" ::: "memory")
#define CP_WAIT0()   asm volatile("cp.async.wait_group 0;" ::: "memory")

#define LDSM4(R0, R1, R2, R3, addr) \
    asm volatile("ldmatrix.sync.aligned.m8n8.x4.shared.b16 {%0,%1,%2,%3}, [%4];" \
                 : "=r"(R0), "=r"(R1), "=r"(R2), "=r"(R3) : "r"(addr))

#define MMA16816(C, A0, A1, A2, A3, B0, B1) \
    asm volatile("mma.sync.aligned.m16n8k16.row.col.f32.f16.f16.f32 " \
                 "{%0,%1,%2,%3}, {%4,%5,%6,%7}, {%8,%9}, {%0,%1,%2,%3};" \
                 : "+f"((C)[0]), "+f"((C)[1]), "+f"((C)[2]), "+f"((C)[3]) \
                 : "r"(A0), "r"(A1), "r"(A2), "r"(A3), "r"(B0), "r"(B1))

// ---------------------------------------------------------------- conversion
__global__ void conv_key_kernel(const float4* __restrict__ key4) {
    const size_t total = (size_t)M_ * H_ / 4;
    __half2* hp = (__half2*)g_keyh;
    for (size_t i = (size_t)blockIdx.x * blockDim.x + threadIdx.x; i < total;
         i += (size_t)gridDim.x * blockDim.x) {
        float4 v = key4[i];
        hp[2*i]   = __floats2half2_rn(v.x, v.y);
        hp[2*i+1] = __floats2half2_rn(v.z, v.w);
    }
}

__global__ void conv_UaT_kernel(const float* __restrict__ Ua) {
    int idx = blockIdx.x * 256 + threadIdx.x;   // idx = n*H + k
    int n = idx >> 10, k = idx & 1023;
    g_UaT[idx] = __float2half_rn(Ua[k * H_ + n]);
}

// ---------------------------------------------------------------- qw^T
__global__ void qwT_kernel(const float* __restrict__ q,
                           const float* __restrict__ Wa,
                           const float* __restrict__ Wab,
                           const float* __restrict__ Uab) {
    int b = blockIdx.y;
    int n = blockIdx.x * 256 + threadIdx.x;
    const float* qb = q + b * H_;
    float acc = Wab[n] + Uab[n];
#pragma unroll 4
    for (int k = 0; k < H_; k++)
        acc = fmaf(qb[k], Wa[k * H_ + n], acc);
    g_qwT[n * B_ + b] = acc;
}

// ---------------------------------------------------------------- energy (HMMA)
// CTA 128x128 of C = key@Ua, single fp16 product, fused tanh epilogue.
// 4 warps in 2x2 grid, 64x64 warp tile (MMA:LDSM = 4.0).
// K staged in 64-element chunks (2 sub-chunks of 32), 2-stage ring.
// Smem tile rows: 64B (32 fp16), 16B chunks swizzled chunk^=(row>>1)&3.
__global__ __launch_bounds__(128, 2)
void energy_mma(const float* __restrict__ va) {
    extern __shared__ __align__(1024) char smem[];
    const uint32_t sb = smem_u32(smem);
    const int tid  = threadIdx.x;
    const int lane = tid & 31, wid = tid >> 5;
    const int warp_m = wid >> 1, warp_n = wid & 1;
    const int n0g = blockIdx.x * 128;
    const int m0  = blockIdx.y * 128;

    // ---- stage loader: 2 subs x 512 chunk-ids (A and B each), 128 threads ----
#define LOAD_STAGE(KT, BUF) do {                                              \
        const int kofs_ = (KT) * 64;                                          \
        const uint32_t st_ = sb + (uint32_t)(BUF) * STAGEB_;                  \
        _Pragma("unroll")                                                     \
        for (int s_ = 0; s_ < 2; s_++) {                                      \
            _Pragma("unroll")                                                 \
            for (int u_ = 0; u_ < 4; u_++) {                                  \
                int id_ = tid + u_ * 128;                                     \
                int r_ = id_ >> 2, c_ = id_ & 3;                              \
                uint32_t off_ = (uint32_t)(s_ * 8192 + r_ * 64                \
                               + 16 * (c_ ^ ((r_ >> 1) & 3)));                \
                size_t gA_ = (size_t)(m0 + r_) * H_ + kofs_ + s_ * 32 + c_ * 8;\
                CP16(st_ + off_, g_keyh + gA_);                               \
                size_t gB_ = (size_t)(n0g + r_) * H_ + kofs_ + s_ * 32 + c_ * 8;\
                CP16(st_ + 16384 + off_, g_UaT + gB_);                        \
            }                                                                 \
        }                                                                     \
    } while (0)

    // prologue: stage 0 + qw slice (1024 float4, 8 per thread)
    LOAD_STAGE(0, 0);
#pragma unroll
    for (int u = 0; u < 8; u++) {
        int idx = tid + u * 128;                 // float4 id 0..1023
        int nl = idx >> 3, b4 = (idx & 7) * 4;   // Qs[n][b]
        CP16(sb + QSOFF_ + (uint32_t)idx * 16,
             g_qwT + (size_t)(n0g + nl) * B_ + b4);
    }
    CP_COMMIT();

    // accumulators c[tm][nt][4]  (64x64 warp tile)
    float c[4][8][4];
#pragma unroll
    for (int i = 0; i < 4; i++)
#pragma unroll
        for (int j = 0; j < 8; j++)
#pragma unroll
            for (int r = 0; r < 4; r++) c[i][j][r] = 0.f;

    const int lrow = lane & 7, jj = lane >> 3;
    const uint32_t swz = (uint32_t)((lrow >> 1) & 3);
    // lane-constant row offsets for ldmatrix
    const uint32_t arow = (uint32_t)((warp_m * 64 + 8 * (jj & 1) + lrow) * 64);
    const uint32_t brow = (uint32_t)((warp_n * 64 + 8 * (jj >> 1) + lrow) * 64);
    const uint32_t achunk = (uint32_t)(jj >> 1);   // k-half from matrix idx
    const uint32_t bchunk = (uint32_t)(jj & 1);

    for (int kt = 0; kt < NSTAGE_; kt++) {
        CP_WAIT0();              // only stage kt's group is outstanding here
        __syncthreads();
        if (kt + 1 < NSTAGE_) { LOAD_STAGE(kt + 1, (kt + 1) & 1); CP_COMMIT(); }

        const uint32_t stg = sb + (uint32_t)(kt & 1) * STAGEB_;

#pragma unroll
        for (int sub = 0; sub < 2; sub++) {
            const uint32_t Ab = stg + (uint32_t)(sub * 8192);
            const uint32_t Bb = stg + 16384u + (uint32_t)(sub * 8192);

#pragma unroll
            for (int ks = 0; ks < 2; ks++) {
                uint32_t bh[8][2];
#pragma unroll
                for (int nt16 = 0; nt16 < 4; nt16++) {
                    uint32_t addr = Bb + brow + (uint32_t)(nt16 * 16 * 64)
                                  + 16u * ((2u * ks + bchunk) ^ swz);
                    LDSM4(bh[2*nt16][0], bh[2*nt16][1], bh[2*nt16+1][0], bh[2*nt16+1][1], addr);
                }
#pragma unroll
                for (int tm = 0; tm < 4; tm++) {
                    uint32_t addr = Ab + arow + (uint32_t)(tm * 16 * 64)
                                  + 16u * ((2u * ks + achunk) ^ swz);
                    uint32_t a0, a1, a2, a3;
                    LDSM4(a0, a1, a2, a3, addr);
#pragma unroll
                    for (int nt = 0; nt < 8; nt++)
                        MMA16816(c[tm][nt], a0, a1, a2, a3, bh[nt][0], bh[nt][1]);
                }
            }
        }
    }

    // ---- fused epilogue: score partials ----
    const int qlane = lane & 3, grp = lane >> 2;
    const float* Qs = (const float*)(smem + QSOFF_);

    float vreg[8][2];
#pragma unroll
    for (int nt = 0; nt < 8; nt++) {
        int n = n0g + warp_n * 64 + nt * 8 + 2 * qlane;
        vreg[nt][0] = __ldg(va + n);
        vreg[nt][1] = __ldg(va + n + 1);
    }

    float psum[4][2];
#pragma unroll
    for (int tm = 0; tm < 4; tm++) { psum[tm][0] = 0.f; psum[tm][1] = 0.f; }

#pragma unroll
    for (int tm = 0; tm < 4; tm++) {
        int bl_ = (tm * 16 + grp) & 31;
        int bh_ = (bl_ + 8) & 31;
#pragma unroll
        for (int nt = 0; nt < 8; nt++) {
            int nl = warp_n * 64 + nt * 8 + 2 * qlane;
            float q00 = Qs[nl * 32 + bl_],       q01 = Qs[(nl + 1) * 32 + bl_];
            float q10 = Qs[nl * 32 + bh_],       q11 = Qs[(nl + 1) * 32 + bh_];
            psum[tm][0] += vreg[nt][0] * tanhf(c[tm][nt][0] + q00)
                         + vreg[nt][1] * tanhf(c[tm][nt][1] + q01);
            psum[tm][1] += vreg[nt][0] * tanhf(c[tm][nt][2] + q10)
                         + vreg[nt][1] * tanhf(c[tm][nt][3] + q11);
        }
    }
    // reduce over the 4 quad lanes (they share the same m rows)
#pragma unroll
    for (int tm = 0; tm < 4; tm++)
#pragma unroll
        for (int h = 0; h < 2; h++) {
            psum[tm][h] += __shfl_xor_sync(0xffffffffu, psum[tm][h], 1);
            psum[tm][h] += __shfl_xor_sync(0xffffffffu, psum[tm][h], 2);
        }
    if (qlane == 0) {
        int plane = blockIdx.x * 2 + warp_n;
#pragma unroll
        for (int tm = 0; tm < 4; tm++)
#pragma unroll
            for (int h = 0; h < 2; h++) {
                int mg = m0 + warp_m * 64 + tm * 16 + h * 8 + grp;
                g_part[(size_t)mg * NPLANES_ + plane] = psum[tm][h];
            }
    }
#undef LOAD_STAGE
}

// ---------------------------------------------------------------- softmax
__global__ void softmax_kernel(float* __restrict__ wout) {
    int b = blockIdx.x, tid = threadIdx.x;
    __shared__ float red[256];
    float sc[8];
#pragma unroll
    for (int u = 0; u < 8; u++) {
        int s = tid + u * 256;
        const float4* pp = (const float4*)&g_part[(size_t)(s * B_ + b) * NPLANES_];
        float v = 0.f;
#pragma unroll
        for (int q = 0; q < 4; q++) {
            float4 t = pp[q];
            v += t.x + t.y + t.z + t.w;
        }
        sc[u] = v;
    }
    float mx = sc[0];
#pragma unroll
    for (int u = 1; u < 8; u++) mx = fmaxf(mx, sc[u]);
    red[tid] = mx; __syncthreads();
    for (int o = 128; o; o >>= 1) {
        if (tid < o) red[tid] = fmaxf(red[tid], red[tid + o]);
        __syncthreads();
    }
    mx = red[0]; __syncthreads();
    float e[8], sum = 0.f;
#pragma unroll
    for (int u = 0; u < 8; u++) { e[u] = expf(sc[u] - mx); sum += e[u]; }
    red[tid] = sum; __syncthreads();
    for (int o = 128; o; o >>= 1) {
        if (tid < o) red[tid] += red[tid + o];
        __syncthreads();
    }
    float inv = 1.f / red[0];
#pragma unroll
    for (int u = 0; u < 8; u++)
        wout[b * S_ + tid + u * 256] = e[u] * inv;
}

// ---------------------------------------------------------------- context
// Reads fp16 key (half DRAM traffic vs fp32 original).
__global__ void ctx_kernel(const float* __restrict__ w) {
    int schunk = blockIdx.x, b = blockIdx.y, tid = threadIdx.x;
    __shared__ float ws[SCHUNK_];
    if (tid < SCHUNK_) ws[tid] = w[b * S_ + schunk * SCHUNK_ + tid];
    __syncthreads();
    int h4 = tid * 4;
    const __half* kb = g_keyh + ((size_t)(schunk * SCHUNK_) * B_ + b) * H_ + h4;
    float4 acc = make_float4(0.f, 0.f, 0.f, 0.f);
#pragma unroll 8
    for (int ss = 0; ss < SCHUNK_; ss++) {
        uint2 raw = *(const uint2*)(kb + (size_t)ss * B_ * H_);
        float2 f0 = __half22float2(*(const __half2*)&raw.x);
        float2 f1 = __half22float2(*(const __half2*)&raw.y);
        float wv = ws[ss];
        acc.x = fmaf(wv, f0.x, acc.x);
        acc.y = fmaf(wv, f0.y, acc.y);
        acc.z = fmaf(wv, f1.x, acc.z);
        acc.w = fmaf(wv, f1.y, acc.w);
    }
    *(float4*)&g_ctxp[(size_t)(schunk * B_ + b) * H_ + h4] = acc;
}

__global__ void ctx_reduce(float* __restrict__ out) {
    int i = blockIdx.x * 256 + threadIdx.x;
    float v = 0.f;
#pragma unroll
    for (int sc = 0; sc < SC_; sc++)
        v += g_ctxp[(size_t)sc * B_ * H_ + i];
    out[i] = v;
}

// ---------------------------------------------------------------- launch
extern "C" void kernel_launch(void* const* d_in, const int* in_sizes, int n_in,
                              void* d_out, int out_size) {
    const float* query = (const float*)d_in[0];
    const float* key   = (const float*)d_in[1];
    const float* Wa_w  = (const float*)d_in[2];
    const float* Wa_b  = (const float*)d_in[3];
    const float* Ua_w  = (const float*)d_in[4];
    const float* Ua_b  = (const float*)d_in[5];
    const float* va_w  = (const float*)d_in[6];
    // d_in[7] = va_b : softmax-shift-invariant, unused.

    float* out = (float*)d_out;
    float* wdst;
    if (out_size >= B_ * H_ + B_ * S_) {
        wdst = out + B_ * H_;
    } else {
        void* p = nullptr;
        cudaGetSymbolAddress(&p, g_wfallback);
        wdst = (float*)p;
    }

    conv_key_kernel<<<16384, 256>>>((const float4*)key);
    conv_UaT_kernel<<<(H_ * H_) / 256, 256>>>(Ua_w);
    qwT_kernel<<<dim3(H_ / 256, B_), 256>>>(query, Wa_w, Wa_b, Ua_b);

    cudaFuncSetAttribute(energy_mma, cudaFuncAttributeMaxDynamicSharedMemorySize, SMEMTOT_);
    energy_mma<<<dim3(8, M_ / 128), 128, SMEMTOT_>>>(va_w);

    softmax_kernel<<<B_, 256>>>(wdst);
    ctx_kernel<<<dim3(SC_, B_), 256>>>(wdst);
    ctx_reduce<<<(B_ * H_) / 256, 256>>>(out);
}

// round 15
// speedup vs baseline: 1.4207x; 1.4207x over previous
#include <cuda_runtime.h>
#include <cuda_fp16.h>
#include <math.h>
#include <stdint.h>

// ---------------------------------------------------------------- constants
#define B_  32
#define S_  2048
#define H_  1024
#define M_  (S_ * B_)          // 65536 flattened key rows (m = s*B + b)
#define SC_ 32                 // context split-K chunks
#define SCHUNK_ (S_ / SC_)     // 64

#define NSTAGE_ 16             // K chunks of 64 elements
#define STAGEB_ 32768          // bytes/stage: A 16K (2 subs) + B 16K (2 subs)
#define QSOFF_  (2 * STAGEB_)  // 65536
#define SMEMTOT_ (QSOFF_ + 16384)   // 81920 (qw slice 128n x 32b floats)
#define NPLANES_ 32            // 8 n-blocks x 4 warp-cols

// ---------------------------------------------------------------- scratch
__device__ __half g_keyh[(size_t)M_ * H_];     // fp16(key), 128 MB
__device__ __half g_UaT[H_ * H_];              // fp16(Ua^T) (rows n, cols k)
__device__ float g_qwT[H_ * B_];               // qw transposed [n][b]
__device__ float g_part[(size_t)NPLANES_ * M_];// [m][plane] score partials
__device__ float g_ctxp[SC_ * B_ * H_];
__device__ float g_wfallback[B_ * S_];

// ---------------------------------------------------------------- asm helpers
__device__ __forceinline__ uint32_t smem_u32(const void* p) {
    uint32_t a;
    asm("{ .reg .u64 t; cvta.to.shared.u64 t, %1; cvt.u32.u64 %0, t; }"
        : "=r"(a) : "l"(p));
    return a;
}

#define CP16(dst, src) \
    asm volatile("cp.async.cg.shared.global [%0], [%1], 16;" \
                 :: "r"(dst), "l"(src) : "memory")
#define CP_COMMIT()  asm volatile("cp.async.commit_group;" ::: "memory")
#define CP_WAIT0()   asm volatile("cp.async.wait_group 0;" ::: "memory")

#define LDSM4(R0, R1, R2, R3, addr) \
    asm volatile("ldmatrix.sync.aligned.m8n8.x4.shared.b16 {%0,%1,%2,%3}, [%4];" \
                 : "=r"(R0), "=r"(R1), "=r"(R2), "=r"(R3) : "r"(addr))

#define MMA16816(C, A0, A1, A2, A3, B0, B1) \
    asm volatile("mma.sync.aligned.m16n8k16.row.col.f32.f16.f16.f32 " \
                 "{%0,%1,%2,%3}, {%4,%5,%6,%7}, {%8,%9}, {%0,%1,%2,%3};" \
                 : "+f"((C)[0]), "+f"((C)[1]), "+f"((C)[2]), "+f"((C)[3]) \
                 : "r"(A0), "r"(A1), "r"(A2), "r"(A3), "r"(B0), "r"(B1))

// ---------------------------------------------------------------- conversion
__global__ void conv_key_kernel(const float4* __restrict__ key4) {
    const size_t total = (size_t)M_ * H_ / 4;
    __half2* hp = (__half2*)g_keyh;
    for (size_t i = (size_t)blockIdx.x * blockDim.x + threadIdx.x; i < total;
         i += (size_t)gridDim.x * blockDim.x) {
        float4 v = key4[i];
        hp[2*i]   = __floats2half2_rn(v.x, v.y);
        hp[2*i+1] = __floats2half2_rn(v.z, v.w);
    }
}

__global__ void conv_UaT_kernel(const float* __restrict__ Ua) {
    int idx = blockIdx.x * 256 + threadIdx.x;   // idx = n*H + k
    int n = idx >> 10, k = idx & 1023;
    g_UaT[idx] = __float2half_rn(Ua[k * H_ + n]);
}

// ---------------------------------------------------------------- qw^T
__global__ void qwT_kernel(const float* __restrict__ q,
                           const float* __restrict__ Wa,
                           const float* __restrict__ Wab,
                           const float* __restrict__ Uab) {
    int b = blockIdx.y;
    int n = blockIdx.x * 256 + threadIdx.x;
    const float* qb = q + b * H_;
    float acc = Wab[n] + Uab[n];
#pragma unroll 4
    for (int k = 0; k < H_; k++)
        acc = fmaf(qb[k], Wa[k * H_ + n], acc);
    g_qwT[n * B_ + b] = acc;
}

// ---------------------------------------------------------------- energy (HMMA)
// CTA 128x128 of C = key@Ua, single fp16 product, fused tanh epilogue.
// 8 warps in 2x4 grid, 64x32 warp tile, 2 CTAs/SM (128 regs).
// Inner loop: batch all 6 LDSM per k-step, then 16 MMAs (1 stall point/ks).
// K staged in 64-element chunks (2 sub-chunks of 32), 2-stage ring.
// Smem tile rows: 64B (32 fp16), 16B chunks swizzled chunk^=(row>>1)&3.
__global__ __launch_bounds__(256, 2)
void energy_mma(const float* __restrict__ va) {
    extern __shared__ __align__(1024) char smem[];
    const uint32_t sb = smem_u32(smem);
    const int tid  = threadIdx.x;
    const int lane = tid & 31, wid = tid >> 5;
    const int warp_m = wid >> 2, warp_n = wid & 3;
    const int n0g = blockIdx.x * 128;
    const int m0  = blockIdx.y * 128;

    // ---- stage loader: 2 sub-chunks x 512 chunk-ids, 2 CP16 each ----
#define LOAD_STAGE(KT, BUF) do {                                              \
        const int kofs_ = (KT) * 64;                                          \
        const uint32_t st_ = sb + (uint32_t)(BUF) * STAGEB_;                  \
        _Pragma("unroll")                                                     \
        for (int s_ = 0; s_ < 2; s_++) {                                      \
            _Pragma("unroll")                                                 \
            for (int u_ = 0; u_ < 2; u_++) {                                  \
                int id_ = tid + u_ * 256;                                     \
                int r_ = id_ >> 2, c_ = id_ & 3;                              \
                uint32_t off_ = (uint32_t)(s_ * 8192 + r_ * 64                \
                               + 16 * (c_ ^ ((r_ >> 1) & 3)));                \
                size_t gA_ = (size_t)(m0 + r_) * H_ + kofs_ + s_ * 32 + c_ * 8;\
                CP16(st_ + off_, g_keyh + gA_);                               \
                size_t gB_ = (size_t)(n0g + r_) * H_ + kofs_ + s_ * 32 + c_ * 8;\
                CP16(st_ + 16384 + off_, g_UaT + gB_);                        \
            }                                                                 \
        }                                                                     \
    } while (0)

    // prologue: stage 0 + qw slice
    LOAD_STAGE(0, 0);
#pragma unroll
    for (int u = 0; u < 4; u++) {
        int idx = tid + u * 256;                 // float4 id 0..1023
        int nl = idx >> 3, b4 = (idx & 7) * 4;   // Qs[n][b]
        CP16(sb + QSOFF_ + (uint32_t)idx * 16,
             g_qwT + (size_t)(n0g + nl) * B_ + b4);
    }
    CP_COMMIT();

    // accumulators c[tm][nt][4]
    float c[4][4][4];
#pragma unroll
    for (int i = 0; i < 4; i++)
#pragma unroll
        for (int j = 0; j < 4; j++)
#pragma unroll
            for (int r = 0; r < 4; r++) c[i][j][r] = 0.f;

    const int lrow = lane & 7, jj = lane >> 3;
    const uint32_t swz = (uint32_t)((lrow >> 1) & 3);
    // lane-constant row offsets for ldmatrix
    const uint32_t arow = (uint32_t)((warp_m * 64 + 8 * (jj & 1) + lrow) * 64);
    const uint32_t brow = (uint32_t)((warp_n * 32 + 8 * (jj >> 1) + lrow) * 64);
    const uint32_t achunk = (uint32_t)(jj >> 1);   // k-half from matrix idx
    const uint32_t bchunk = (uint32_t)(jj & 1);

    for (int kt = 0; kt < NSTAGE_; kt++) {
        CP_WAIT0();              // only stage kt's group is outstanding here
        __syncthreads();
        if (kt + 1 < NSTAGE_) { LOAD_STAGE(kt + 1, (kt + 1) & 1); CP_COMMIT(); }

        const uint32_t stg = sb + (uint32_t)(kt & 1) * STAGEB_;

#pragma unroll
        for (int sub = 0; sub < 2; sub++) {
            const uint32_t Ab = stg + (uint32_t)(sub * 8192);
            const uint32_t Bb = stg + 16384u + (uint32_t)(sub * 8192);

#pragma unroll
            for (int ks = 0; ks < 2; ks++) {
                // ---- batch ALL loads for this k-step ----
                uint32_t bh[4][2];
                uint32_t ar[4][4];
#pragma unroll
                for (int nt16 = 0; nt16 < 2; nt16++) {
                    uint32_t addr = Bb + brow + (uint32_t)(nt16 * 16 * 64)
                                  + 16u * ((2u * ks + bchunk) ^ swz);
                    LDSM4(bh[2*nt16][0], bh[2*nt16][1], bh[2*nt16+1][0], bh[2*nt16+1][1], addr);
                }
#pragma unroll
                for (int tm = 0; tm < 4; tm++) {
                    uint32_t addr = Ab + arow + (uint32_t)(tm * 16 * 64)
                                  + 16u * ((2u * ks + achunk) ^ swz);
                    LDSM4(ar[tm][0], ar[tm][1], ar[tm][2], ar[tm][3], addr);
                }
                // ---- then all 16 MMAs, dependency-free amongst themselves ----
#pragma unroll
                for (int tm = 0; tm < 4; tm++)
#pragma unroll
                    for (int nt = 0; nt < 4; nt++)
                        MMA16816(c[tm][nt], ar[tm][0], ar[tm][1], ar[tm][2], ar[tm][3],
                                 bh[nt][0], bh[nt][1]);
            }
        }
    }

    // ---- fused epilogue: score partials ----
    const int qlane = lane & 3, grp = lane >> 2;
    const float* Qs = (const float*)(smem + QSOFF_);

    float vreg[4][2];
#pragma unroll
    for (int nt = 0; nt < 4; nt++) {
        int n = n0g + warp_n * 32 + nt * 8 + 2 * qlane;
        vreg[nt][0] = __ldg(va + n);
        vreg[nt][1] = __ldg(va + n + 1);
    }

    float psum[4][2];
#pragma unroll
    for (int tm = 0; tm < 4; tm++) { psum[tm][0] = 0.f; psum[tm][1] = 0.f; }

#pragma unroll
    for (int tm = 0; tm < 4; tm++) {
        int bl_ = (tm * 16 + grp) & 31;
        int bh_ = (bl_ + 8) & 31;
#pragma unroll
        for (int nt = 0; nt < 4; nt++) {
            int nl = warp_n * 32 + nt * 8 + 2 * qlane;
            float q00 = Qs[nl * 32 + bl_],       q01 = Qs[(nl + 1) * 32 + bl_];
            float q10 = Qs[nl * 32 + bh_],       q11 = Qs[(nl + 1) * 32 + bh_];
            psum[tm][0] += vreg[nt][0] * tanhf(c[tm][nt][0] + q00)
                         + vreg[nt][1] * tanhf(c[tm][nt][1] + q01);
            psum[tm][1] += vreg[nt][0] * tanhf(c[tm][nt][2] + q10)
                         + vreg[nt][1] * tanhf(c[tm][nt][3] + q11);
        }
    }
    // reduce over the 4 quad lanes (they share the same m rows)
#pragma unroll
    for (int tm = 0; tm < 4; tm++)
#pragma unroll
        for (int h = 0; h < 2; h++) {
            psum[tm][h] += __shfl_xor_sync(0xffffffffu, psum[tm][h], 1);
            psum[tm][h] += __shfl_xor_sync(0xffffffffu, psum[tm][h], 2);
        }
    if (qlane == 0) {
        int plane = blockIdx.x * 4 + warp_n;
#pragma unroll
        for (int tm = 0; tm < 4; tm++)
#pragma unroll
            for (int h = 0; h < 2; h++) {
                int mg = m0 + warp_m * 64 + tm * 16 + h * 8 + grp;
                g_part[(size_t)mg * NPLANES_ + plane] = psum[tm][h];
            }
    }
#undef LOAD_STAGE
}

// ---------------------------------------------------------------- softmax
__global__ void softmax_kernel(float* __restrict__ wout) {
    int b = blockIdx.x, tid = threadIdx.x;
    __shared__ float red[256];
    float sc[8];
#pragma unroll
    for (int u = 0; u < 8; u++) {
        int s = tid + u * 256;
        const float4* pp = (const float4*)&g_part[(size_t)(s * B_ + b) * NPLANES_];
        float v = 0.f;
#pragma unroll
        for (int q = 0; q < 8; q++) {
            float4 t = pp[q];
            v += t.x + t.y + t.z + t.w;
        }
        sc[u] = v;
    }
    float mx = sc[0];
#pragma unroll
    for (int u = 1; u < 8; u++) mx = fmaxf(mx, sc[u]);
    red[tid] = mx; __syncthreads();
    for (int o = 128; o; o >>= 1) {
        if (tid < o) red[tid] = fmaxf(red[tid], red[tid + o]);
        __syncthreads();
    }
    mx = red[0]; __syncthreads();
    float e[8], sum = 0.f;
#pragma unroll
    for (int u = 0; u < 8; u++) { e[u] = expf(sc[u] - mx); sum += e[u]; }
    red[tid] = sum; __syncthreads();
    for (int o = 128; o; o >>= 1) {
        if (tid < o) red[tid] += red[tid + o];
        __syncthreads();
    }
    float inv = 1.f / red[0];
#pragma unroll
    for (int u = 0; u < 8; u++)
        wout[b * S_ + tid + u * 256] = e[u] * inv;
}

// ---------------------------------------------------------------- context
// Reads fp16 key (half DRAM traffic vs fp32 original).
__global__ void ctx_kernel(const float* __restrict__ w) {
    int schunk = blockIdx.x, b = blockIdx.y, tid = threadIdx.x;
    __shared__ float ws[SCHUNK_];
    if (tid < SCHUNK_) ws[tid] = w[b * S_ + schunk * SCHUNK_ + tid];
    __syncthreads();
    int h4 = tid * 4;
    const __half* kb = g_keyh + ((size_t)(schunk * SCHUNK_) * B_ + b) * H_ + h4;
    float4 acc = make_float4(0.f, 0.f, 0.f, 0.f);
#pragma unroll 8
    for (int ss = 0; ss < SCHUNK_; ss++) {
        uint2 raw = *(const uint2*)(kb + (size_t)ss * B_ * H_);
        float2 f0 = __half22float2(*(const __half2*)&raw.x);
        float2 f1 = __half22float2(*(const __half2*)&raw.y);
        float wv = ws[ss];
        acc.x = fmaf(wv, f0.x, acc.x);
        acc.y = fmaf(wv, f0.y, acc.y);
        acc.z = fmaf(wv, f1.x, acc.z);
        acc.w = fmaf(wv, f1.y, acc.w);
    }
    *(float4*)&g_ctxp[(size_t)(schunk * B_ + b) * H_ + h4] = acc;
}

__global__ void ctx_reduce(float* __restrict__ out) {
    int i = blockIdx.x * 256 + threadIdx.x;
    float v = 0.f;
#pragma unroll
    for (int sc = 0; sc < SC_; sc++)
        v += g_ctxp[(size_t)sc * B_ * H_ + i];
    out[i] = v;
}

// ---------------------------------------------------------------- launch
extern "C" void kernel_launch(void* const* d_in, const int* in_sizes, int n_in,
                              void* d_out, int out_size) {
    const float* query = (const float*)d_in[0];
    const float* key   = (const float*)d_in[1];
    const float* Wa_w  = (const float*)d_in[2];
    const float* Wa_b  = (const float*)d_in[3];
    const float* Ua_w  = (const float*)d_in[4];
    const float* Ua_b  = (const float*)d_in[5];
    const float* va_w  = (const float*)d_in[6];
    // d_in[7] = va_b : softmax-shift-invariant, unused.

    float* out = (float*)d_out;
    float* wdst;
    if (out_size >= B_ * H_ + B_ * S_) {
        wdst = out + B_ * H_;
    } else {
        void* p = nullptr;
        cudaGetSymbolAddress(&p, g_wfallback);
        wdst = (float*)p;
    }

    conv_key_kernel<<<16384, 256>>>((const float4*)key);
    conv_UaT_kernel<<<(H_ * H_) / 256, 256>>>(Ua_w);
    qwT_kernel<<<dim3(H_ / 256, B_), 256>>>(query, Wa_w, Wa_b, Ua_b);

    cudaFuncSetAttribute(energy_mma, cudaFuncAttributeMaxDynamicSharedMemorySize, SMEMTOT_);
    energy_mma<<<dim3(8, M_ / 128), 256, SMEMTOT_>>>(va_w);

    softmax_kernel<<<B_, 256>>>(wdst);
    ctx_kernel<<<dim3(SC_, B_), 256>>>(wdst);
    ctx_reduce<<<(B_ * H_) / 256, 256>>>(out);
}